// round 7
// baseline (speedup 1.0000x reference)
#include <cuda_runtime.h>
#include <cuda_bf16.h>

#define RESTRICT __restrict__

constexpr int SEQL = 512, NB = 16, EMB = 512, MR = SEQL * NB;
constexpr int QKVLD = NB * 3 * EMB;   // 24576: per-s stride in qkv buffer

// ---- one big static scratch (377 MB), partitioned by offsets ----
__device__ float g_scratch[94396416];
// offsets (floats)
constexpr size_t O_LN1 = 0;           // 8192x512
constexpr size_t O_QKV = 4194304;     // 8192x1536
constexpr size_t O_SC  = 16777216;    // 128 heads x 512x512
constexpr size_t O_O   = 50331648;    // 8192x512 (S,B)
constexpr size_t O_X1  = 54525952;    // 8192x512 (S,B)
constexpr size_t O_XB  = 58720256;    // 8192x512 (B,S)
constexpr size_t O_HSB = 62914560;    // 8192x512 (S,B)
constexpr size_t O_LG  = 67108864;    // 8192x128
constexpr size_t O_X2  = 68157440;    // 8192x512 (S,B)
constexpr size_t O_H2  = 72351744;    // 8192x512
constexpr size_t O_FF  = 76546048;    // 8192x2048
constexpr size_t O_SI  = 93323264;    // 8192x128
constexpr size_t O_CT  = 94371840;    // 8192x3

// ---- f32x2 helpers ----
__device__ __forceinline__ unsigned long long pk2(float x, float y) {
    unsigned long long r;
    asm("mov.b64 %0, {%1, %2};" : "=l"(r) : "f"(x), "f"(y));
    return r;
}
__device__ __forceinline__ void ffma2(unsigned long long& d, unsigned long long a,
                                      unsigned long long b) {
    asm("fma.rn.f32x2 %0, %1, %2, %0;" : "+l"(d) : "l"(a), "l"(b));
}
__device__ __forceinline__ float2 upk2(unsigned long long v) {
    float2 r;
    asm("mov.b64 {%0, %1}, %2;" : "=f"(r.x), "=f"(r.y) : "l"(v));
    return r;
}

__device__ __forceinline__ float nonsat_f(float x) {
    float y = x;
#pragma unroll
    for (int i = 0; i < 8; i++) {
        float y2 = y * y;
        y = __fdividef(__fmaf_rn(0.66666667f * y2, y, x), y2 + 1.0f);
    }
    return y;
}

// ---- LayerNorm: block(128) per row of 512 ----
__global__ void ln_kernel(const float* RESTRICT in, const float* RESTRICT g,
                          const float* RESTRICT b, float* RESTRICT out) {
    int row = blockIdx.x, t = threadIdx.x;
    float4 v = ((const float4*)(in + (size_t)row * EMB))[t];
    float s = v.x + v.y + v.z + v.w;
    float sq = v.x * v.x + v.y * v.y + v.z * v.z + v.w * v.w;
    __shared__ float ss[4], ssq[4];
#pragma unroll
    for (int o = 16; o > 0; o >>= 1) {
        s += __shfl_down_sync(0xffffffffu, s, o);
        sq += __shfl_down_sync(0xffffffffu, sq, o);
    }
    int w = t >> 5, l = t & 31;
    if (l == 0) { ss[w] = s; ssq[w] = sq; }
    __syncthreads();
    s = ss[0] + ss[1] + ss[2] + ss[3];
    sq = ssq[0] + ssq[1] + ssq[2] + ssq[3];
    float mean = s * (1.0f / EMB);
    float rstd = rsqrtf(sq * (1.0f / EMB) - mean * mean + 1e-5f);
    float4 gv = ((const float4*)g)[t], bv = ((const float4*)b)[t];
    float4 o4;
    o4.x = (v.x - mean) * rstd * gv.x + bv.x;
    o4.y = (v.y - mean) * rstd * gv.y + bv.y;
    o4.z = (v.z - mean) * rstd * gv.z + bv.z;
    o4.w = (v.w - mean) * rstd * gv.w + bv.w;
    ((float4*)(out + (size_t)row * EMB))[t] = o4;
}

// ---- generic NT GEMM: C = A(MxK)*W(NxK)^T, 128x128x8 tiles, 256 thr ----
enum { EP_NONE = 0, EP_RELU, EP_NONSAT, EP_RESID, EP_HALF };

template <int EPI, bool ACCUM>
__global__ void __launch_bounds__(256) gemm_nt(
    const float* RESTRICT A, int lda, const float* RESTRICT W, int ldw,
    const float* RESTRICT bias, const float* RESTRICT resid, int ldr,
    float* RESTRICT C, int ldc, int K) {
    __shared__ float As[8][132], Bs[8][132];
    const int tid = threadIdx.x;
    const int tr = tid >> 4, tc = tid & 15;
    const int lrow = tid >> 1, lk = (tid & 1) * 4;
    const float* Ab = A + (size_t)(blockIdx.y * 128 + lrow) * lda + lk;
    const float* Wb = W + (size_t)(blockIdx.x * 128 + lrow) * ldw + lk;

    unsigned long long acc[8][4];
#pragma unroll
    for (int i = 0; i < 8; i++)
#pragma unroll
        for (int j = 0; j < 4; j++) acc[i][j] = 0ull;

    float4 av = *(const float4*)Ab;
    float4 wv = *(const float4*)Wb;
    for (int k0 = 0; k0 < K; k0 += 8) {
        As[lk + 0][lrow] = av.x; As[lk + 1][lrow] = av.y;
        As[lk + 2][lrow] = av.z; As[lk + 3][lrow] = av.w;
        Bs[lk + 0][lrow] = wv.x; Bs[lk + 1][lrow] = wv.y;
        Bs[lk + 2][lrow] = wv.z; Bs[lk + 3][lrow] = wv.w;
        __syncthreads();
        if (k0 + 8 < K) {
            av = *(const float4*)(Ab + k0 + 8);
            wv = *(const float4*)(Wb + k0 + 8);
        }
#pragma unroll
        for (int kk = 0; kk < 8; kk++) {
            float a[8];
            unsigned long long b2[4];
#pragma unroll
            for (int i = 0; i < 8; i++) a[i] = As[kk][tr * 8 + i];
#pragma unroll
            for (int j = 0; j < 4; j++)
                b2[j] = pk2(Bs[kk][tc * 8 + 2 * j], Bs[kk][tc * 8 + 2 * j + 1]);
#pragma unroll
            for (int i = 0; i < 8; i++) {
                unsigned long long a2 = pk2(a[i], a[i]);
#pragma unroll
                for (int j = 0; j < 4; j++) ffma2(acc[i][j], a2, b2[j]);
            }
        }
        __syncthreads();
    }
    const int m0 = blockIdx.y * 128 + tr * 8;
    const int n0 = blockIdx.x * 128 + tc * 8;
#pragma unroll
    for (int i = 0; i < 8; i++) {
        float v[8];
#pragma unroll
        for (int j = 0; j < 4; j++) {
            float2 p = upk2(acc[i][j]);
            v[2 * j] = p.x; v[2 * j + 1] = p.y;
        }
        if (bias) {
#pragma unroll
            for (int j = 0; j < 8; j++) v[j] += bias[n0 + j];
        }
        float* crow = C + (size_t)(m0 + i) * ldc + n0;
        if (ACCUM) {
            float4 c0 = *(const float4*)crow, c1 = *(const float4*)(crow + 4);
            v[0] += c0.x; v[1] += c0.y; v[2] += c0.z; v[3] += c0.w;
            v[4] += c1.x; v[5] += c1.y; v[6] += c1.z; v[7] += c1.w;
        }
        if (EPI == EP_RELU) {
#pragma unroll
            for (int j = 0; j < 8; j++) v[j] = fmaxf(v[j], 0.0f);
        } else if (EPI == EP_NONSAT) {
#pragma unroll
            for (int j = 0; j < 8; j++) v[j] = nonsat_f(v[j]);
        } else if (EPI == EP_RESID) {
            const float* rr = resid + (size_t)(m0 + i) * ldr + n0;
            float4 r0 = *(const float4*)rr, r1 = *(const float4*)(rr + 4);
            v[0] += r0.x; v[1] += r0.y; v[2] += r0.z; v[3] += r0.w;
            v[4] += r1.x; v[5] += r1.y; v[6] += r1.z; v[7] += r1.w;
        } else if (EPI == EP_HALF) {
            const float* rr = resid + (size_t)(m0 + i) * ldr + n0;
            float4 r0 = *(const float4*)rr, r1 = *(const float4*)(rr + 4);
            v[0] = 0.5f * (v[0] + r0.x); v[1] = 0.5f * (v[1] + r0.y);
            v[2] = 0.5f * (v[2] + r0.z); v[3] = 0.5f * (v[3] + r0.w);
            v[4] = 0.5f * (v[4] + r1.x); v[5] = 0.5f * (v[5] + r1.y);
            v[6] = 0.5f * (v[6] + r1.z); v[7] = 0.5f * (v[7] + r1.w);
        }
        *(float4*)crow = make_float4(v[0], v[1], v[2], v[3]);
        *(float4*)(crow + 4) = make_float4(v[4], v[5], v[6], v[7]);
    }
}

// ---- attention scores: per (b,h) QK^T, K=64, scaled + causal ----
__global__ void __launch_bounds__(256) attn_scores(const float* RESTRICT qkv,
                                                   float* RESTRICT scores) {
    __shared__ float As[8][132], Bs[8][132];
    const int head = blockIdx.z, b = head >> 3, h = head & 7;
    const int tid = threadIdx.x;
    const int tr = tid >> 4, tc = tid & 15;
    const int lrow = tid >> 1, lk = (tid & 1) * 4;
    const float* qb = qkv + (size_t)(blockIdx.y * 128 + lrow) * QKVLD + b * 1536 + h * 64 + lk;
    const float* kb = qkv + (size_t)(blockIdx.x * 128 + lrow) * QKVLD + b * 1536 + 512 + h * 64 + lk;
    unsigned long long acc[8][4];
#pragma unroll
    for (int i = 0; i < 8; i++)
#pragma unroll
        for (int j = 0; j < 4; j++) acc[i][j] = 0ull;
    float4 av = *(const float4*)qb;
    float4 wv = *(const float4*)kb;
    for (int k0 = 0; k0 < 64; k0 += 8) {
        As[lk + 0][lrow] = av.x; As[lk + 1][lrow] = av.y;
        As[lk + 2][lrow] = av.z; As[lk + 3][lrow] = av.w;
        Bs[lk + 0][lrow] = wv.x; Bs[lk + 1][lrow] = wv.y;
        Bs[lk + 2][lrow] = wv.z; Bs[lk + 3][lrow] = wv.w;
        __syncthreads();
        if (k0 + 8 < 64) { av = *(const float4*)(qb + k0 + 8); wv = *(const float4*)(kb + k0 + 8); }
#pragma unroll
        for (int kk = 0; kk < 8; kk++) {
            float a[8];
            unsigned long long b2[4];
#pragma unroll
            for (int i = 0; i < 8; i++) a[i] = As[kk][tr * 8 + i];
#pragma unroll
            for (int j = 0; j < 4; j++)
                b2[j] = pk2(Bs[kk][tc * 8 + 2 * j], Bs[kk][tc * 8 + 2 * j + 1]);
#pragma unroll
            for (int i = 0; i < 8; i++) {
                unsigned long long a2 = pk2(a[i], a[i]);
#pragma unroll
                for (int j = 0; j < 4; j++) ffma2(acc[i][j], a2, b2[j]);
            }
        }
        __syncthreads();
    }
    const int q0 = blockIdx.y * 128 + tr * 8, kk0 = blockIdx.x * 128 + tc * 8;
    const float NEGINF = __int_as_float(0xff800000);
    float* sbase = scores + (size_t)head * SEQL * SEQL;
#pragma unroll
    for (int i = 0; i < 8; i++) {
        int q = q0 + i;
        float v[8];
#pragma unroll
        for (int j = 0; j < 4; j++) {
            float2 p = upk2(acc[i][j]);
            v[2 * j] = p.x; v[2 * j + 1] = p.y;
        }
#pragma unroll
        for (int j = 0; j < 8; j++) {
            v[j] *= 0.125f;
            if (kk0 + j > q) v[j] = NEGINF;
        }
        float* crow = sbase + (size_t)q * SEQL + kk0;
        *(float4*)crow = make_float4(v[0], v[1], v[2], v[3]);
        *(float4*)(crow + 4) = make_float4(v[4], v[5], v[6], v[7]);
    }
}

// ---- softmax over 512, warp per row, with key mask ----
__global__ void softmax512(float* RESTRICT sc, const unsigned char* RESTRICT mask) {
    int row = blockIdx.x * 8 + (threadIdx.x >> 5);     // row in [0, 128*512)
    int l = threadIdx.x & 31;
    int b = row >> 12;
    const float NEGINF = __int_as_float(0xff800000);
    float4* p = (float4*)(sc + (size_t)row * SEQL);
    const uchar4* m4 = (const uchar4*)(mask + b * SEQL);
    float4 v[4];
    float mx = -3.402823466e38f;
#pragma unroll
    for (int w = 0; w < 4; w++) {
        int i = l + w * 32;
        v[w] = p[i];
        uchar4 m = m4[i];
        if (m.x) v[w].x = NEGINF;
        if (m.y) v[w].y = NEGINF;
        if (m.z) v[w].z = NEGINF;
        if (m.w) v[w].w = NEGINF;
        mx = fmaxf(mx, fmaxf(fmaxf(v[w].x, v[w].y), fmaxf(v[w].z, v[w].w)));
    }
#pragma unroll
    for (int o = 16; o > 0; o >>= 1) mx = fmaxf(mx, __shfl_xor_sync(0xffffffffu, mx, o));
    float s = 0.0f;
#pragma unroll
    for (int w = 0; w < 4; w++) {
        v[w].x = __expf(v[w].x - mx); v[w].y = __expf(v[w].y - mx);
        v[w].z = __expf(v[w].z - mx); v[w].w = __expf(v[w].w - mx);
        s += v[w].x + v[w].y + v[w].z + v[w].w;
    }
#pragma unroll
    for (int o = 16; o > 0; o >>= 1) s += __shfl_xor_sync(0xffffffffu, s, o);
    float inv = __fdividef(1.0f, s);
#pragma unroll
    for (int w = 0; w < 4; w++) {
        v[w].x *= inv; v[w].y *= inv; v[w].z *= inv; v[w].w *= inv;
        p[l + w * 32] = v[w];
    }
}

// ---- per-head O = P(512x512) @ V(512x64) -> (S,B,E) ----
__global__ void __launch_bounds__(256) attn_av(const float* RESTRICT qkv,
                                               const float* RESTRICT scores,
                                               float* RESTRICT O) {
    __shared__ float As[8][132], Bs[8][68];
    const int head = blockIdx.z, b = head >> 3, h = head & 7;
    const int tid = threadIdx.x;
    const int tr = tid >> 4, tc = tid & 15;
    const int lrow = tid >> 1, lk = (tid & 1) * 4;
    const float* sc = scores + (size_t)head * SEQL * SEQL +
                      (size_t)(blockIdx.y * 128 + lrow) * SEQL + lk;
    const float* vbase = qkv + (size_t)b * 1536 + 1024 + (size_t)h * 64;
    const int brow = tid >> 4, bcol = (tid & 15) * 4;
    unsigned long long acc[8][2];
#pragma unroll
    for (int i = 0; i < 8; i++) { acc[i][0] = 0ull; acc[i][1] = 0ull; }
    float4 av = *(const float4*)sc;
    float4 vv = make_float4(0, 0, 0, 0);
    if (tid < 128) vv = *(const float4*)(vbase + (size_t)brow * QKVLD + bcol);
    for (int k0 = 0; k0 < 512; k0 += 8) {
        As[lk + 0][lrow] = av.x; As[lk + 1][lrow] = av.y;
        As[lk + 2][lrow] = av.z; As[lk + 3][lrow] = av.w;
        if (tid < 128) *(float4*)&Bs[brow][bcol] = vv;
        __syncthreads();
        if (k0 + 8 < 512) {
            av = *(const float4*)(sc + k0 + 8);
            if (tid < 128)
                vv = *(const float4*)(vbase + (size_t)(k0 + 8 + brow) * QKVLD + bcol);
        }
#pragma unroll
        for (int kk = 0; kk < 8; kk++) {
            float a[8];
            unsigned long long b0 = pk2(Bs[kk][tc * 4 + 0], Bs[kk][tc * 4 + 1]);
            unsigned long long b1 = pk2(Bs[kk][tc * 4 + 2], Bs[kk][tc * 4 + 3]);
#pragma unroll
            for (int i = 0; i < 8; i++) a[i] = As[kk][tr * 8 + i];
#pragma unroll
            for (int i = 0; i < 8; i++) {
                unsigned long long a2 = pk2(a[i], a[i]);
                ffma2(acc[i][0], a2, b0);
                ffma2(acc[i][1], a2, b1);
            }
        }
        __syncthreads();
    }
    const int q0 = blockIdx.y * 128 + tr * 8, d0 = tc * 4;
#pragma unroll
    for (int i = 0; i < 8; i++) {
        float2 p0 = upk2(acc[i][0]), p1 = upk2(acc[i][1]);
        *(float4*)(O + (size_t)((q0 + i) * NB + b) * EMB + h * 64 + d0) =
            make_float4(p0.x, p0.y, p1.x, p1.y);
    }
}

// ---- layout transposes, block(128) per out row ----
__global__ void tr_sb2bs(const float* RESTRICT in, float* RESTRICT out) {
    int r = blockIdx.x, b = r >> 9, s = r & 511;
    ((float4*)(out + (size_t)r * EMB))[threadIdx.x] =
        ((const float4*)(in + (size_t)(s * NB + b) * EMB))[threadIdx.x];
}
__global__ void tr_bs2sb(const float* RESTRICT in, float* RESTRICT out) {
    int r = blockIdx.x, s = r >> 4, b = r & 15;   // out row r = s*16+b
    ((float4*)(out + (size_t)r * EMB))[threadIdx.x] =
        ((const float4*)(in + (size_t)(b * SEQL + s) * EMB))[threadIdx.x];
}

// ---- softmax over 128, warp per row ----
__global__ void softmax128(float* RESTRICT p) {
    int row = blockIdx.x * 8 + (threadIdx.x >> 5);
    int l = threadIdx.x & 31;
    float4 v = ((float4*)(p + (size_t)row * 128))[l];
    float mx = fmaxf(fmaxf(v.x, v.y), fmaxf(v.z, v.w));
#pragma unroll
    for (int o = 16; o > 0; o >>= 1) mx = fmaxf(mx, __shfl_xor_sync(0xffffffffu, mx, o));
    v.x = __expf(v.x - mx); v.y = __expf(v.y - mx);
    v.z = __expf(v.z - mx); v.w = __expf(v.w - mx);
    float s = v.x + v.y + v.z + v.w;
#pragma unroll
    for (int o = 16; o > 0; o >>= 1) s += __shfl_xor_sync(0xffffffffu, s, o);
    float inv = __fdividef(1.0f, s);
    v.x *= inv; v.y *= inv; v.z *= inv; v.w *= inv;
    ((float4*)(p + (size_t)row * 128))[l] = v;
}

// ---- controls = softmax(hidden @ A_w^T + A_b), block(128) per row ----
__global__ void controls_kernel(const float* RESTRICT hid, const float* RESTRICT Aw,
                                const float* RESTRICT Ab, float* RESTRICT ctl) {
    int r = blockIdx.x, t = threadIdx.x;
    float4 h = ((const float4*)(hid + (size_t)r * EMB))[t];
    float4 a0 = ((const float4*)Aw)[t];
    float4 a1 = ((const float4*)(Aw + 512))[t];
    float4 a2 = ((const float4*)(Aw + 1024))[t];
    float p0 = h.x * a0.x + h.y * a0.y + h.z * a0.z + h.w * a0.w;
    float p1 = h.x * a1.x + h.y * a1.y + h.z * a1.z + h.w * a1.w;
    float p2 = h.x * a2.x + h.y * a2.y + h.z * a2.z + h.w * a2.w;
#pragma unroll
    for (int o = 16; o > 0; o >>= 1) {
        p0 += __shfl_down_sync(0xffffffffu, p0, o);
        p1 += __shfl_down_sync(0xffffffffu, p1, o);
        p2 += __shfl_down_sync(0xffffffffu, p2, o);
    }
    __shared__ float sm[3][4];
    int w = t >> 5, l = t & 31;
    if (l == 0) { sm[0][w] = p0; sm[1][w] = p1; sm[2][w] = p2; }
    __syncthreads();
    if (t == 0) {
        float c0 = sm[0][0] + sm[0][1] + sm[0][2] + sm[0][3] + Ab[0];
        float c1 = sm[1][0] + sm[1][1] + sm[1][2] + sm[1][3] + Ab[1];
        float c2 = sm[2][0] + sm[2][1] + sm[2][2] + sm[2][3] + Ab[2];
        float m = fmaxf(c0, fmaxf(c1, c2));
        float e0 = __expf(c0 - m), e1 = __expf(c1 - m), e2 = __expf(c2 - m);
        float inv = __fdividef(1.0f, e0 + e1 + e2);
        ctl[r * 3 + 0] = e0 * inv; ctl[r * 3 + 1] = e1 * inv; ctl[r * 3 + 2] = e2 * inv;
    }
}

// ---- stack update, block(256) per (b,s) row ----
__global__ void stack_kernel(const float* RESTRICT prev, const float* RESTRICT sinp,
                             const float* RESTRICT ctl, float* RESTRICT out) {
    int r = blockIdx.x;
    __shared__ float sp[48 * 128];
    __shared__ float si[128];
    const float4* pin = (const float4*)(prev + (size_t)r * 6144);
    float4* sp4 = (float4*)sp;
    for (int i = threadIdx.x; i < 1536; i += 256) sp4[i] = pin[i];
    if (threadIdx.x < 32)
        ((float4*)si)[threadIdx.x] = ((const float4*)(sinp + (size_t)r * 128))[threadIdx.x];
    __syncthreads();
    float apu = ctl[r * 3 + 0], apo = ctl[r * 3 + 1], ano = ctl[r * 3 + 2];
    float4* o4 = (float4*)(out + (size_t)r * 6144);
    for (int i = threadIdx.x; i < 1536; i += 256) {
        int d = i >> 5, w4 = i & 31;
        float4 pv = sp4[i];
        float4 up = (d == 0) ? ((float4*)si)[w4] : sp4[i - 32];
        float4 dn = (d == 47) ? make_float4(0, 0, 0, 0) : sp4[i + 32];
        float4 o;
        o.x = ano * pv.x + apu * up.x + apo * dn.x;
        o.y = ano * pv.y + apu * up.y + apo * dn.y;
        o.z = ano * pv.z + apu * up.z + apo * dn.z;
        o.w = ano * pv.w + apu * up.w + apo * dn.w;
        o4[i] = o;
    }
}

extern "C" void kernel_launch(void* const* d_in, const int* in_sizes, int n_in,
                              void* d_out, int out_size) {
    const float* x_in   = (const float*)d_in[0];
    const float* h_prev = (const float*)d_in[1];
    const float* s_prev = (const float*)d_in[2];
    const unsigned char* k_mask = (const unsigned char*)d_in[3];
    const float* in_w   = (const float*)d_in[4];
    const float* in_b   = (const float*)d_in[5];
    const float* out_w  = (const float*)d_in[6];
    const float* out_b  = (const float*)d_in[7];
    const float* ln1g = (const float*)d_in[8],  *ln1b = (const float*)d_in[9];
    const float* ln2g = (const float*)d_in[10], *ln2b = (const float*)d_in[11];
    const float* ffw1 = (const float*)d_in[12], *ffb1 = (const float*)d_in[13];
    const float* ffw2 = (const float*)d_in[14], *ffb2 = (const float*)d_in[15];
    const float* Ww = (const float*)d_in[16], *Wb = (const float*)d_in[17];
    const float* Rw = (const float*)d_in[18], *Rb = (const float*)d_in[19];
    const float* Pw = (const float*)d_in[20], *Pb = (const float*)d_in[21];
    const float* Vw = (const float*)d_in[22];
    const float* Uw = (const float*)d_in[23];
    const float* Aw = (const float*)d_in[24], *Ab = (const float*)d_in[25];
    const float* Dw = (const float*)d_in[26], *Db = (const float*)d_in[27];

    float* sb;
    cudaGetSymbolAddress((void**)&sb, g_scratch);
    float* ln1 = sb + O_LN1;  float* qkv = sb + O_QKV;  float* scr = sb + O_SC;
    float* obuf = sb + O_O;   float* x1 = sb + O_X1;    float* xb = sb + O_XB;
    float* hsb = sb + O_HSB;  float* lg = sb + O_LG;    float* x2 = sb + O_X2;
    float* h2 = sb + O_H2;    float* ff = sb + O_FF;    float* si = sb + O_SI;
    float* ct = sb + O_CT;

    float* out_x = (float*)d_out;
    float* out_h = out_x + (size_t)MR * EMB;
    float* out_s = out_h + (size_t)MR * EMB;

    // 1. ln1 = LN(x_in)
    ln_kernel<<<MR, 128>>>(x_in, ln1g, ln1b, ln1);
    // 2. qkv
    gemm_nt<EP_NONE, false><<<dim3(12, 64), 256>>>(ln1, 512, in_w, 512, in_b,
                                                   nullptr, 0, qkv, 1536, 512);
    // 3-5. attention
    attn_scores<<<dim3(4, 4, 128), 256>>>(qkv, scr);
    softmax512<<<128 * 512 / 8, 256>>>(scr, k_mask);
    attn_av<<<dim3(1, 4, 128), 256>>>(qkv, scr, obuf);
    // 6. x1 = x_in + o @ out_w^T + out_b
    gemm_nt<EP_RESID, false><<<dim3(4, 64), 256>>>(obuf, 512, out_w, 512, out_b,
                                                   x_in, 512, x1, 512, 512);
    // 7. xb = (B,S) layout of x1
    tr_sb2bs<<<MR, 128>>>(x1, xb);
    // 8-10. hidden = nonsat(xb@W^T + Wb + hp@R^T + Rb + stack0@P^T + Pb) -> out_h
    gemm_nt<EP_NONE, false><<<dim3(4, 64), 256>>>(xb, 512, Ww, 512, Wb,
                                                  nullptr, 0, out_h, 512, 512);
    gemm_nt<EP_NONE, true><<<dim3(4, 64), 256>>>(h_prev, 512, Rw, 512, Rb,
                                                 nullptr, 0, out_h, 512, 512);
    gemm_nt<EP_NONSAT, true><<<dim3(4, 64), 256>>>(s_prev, 6144, Pw, 128, Pb,
                                                   nullptr, 0, out_h, 512, 128);
    // 11. hsb = (S,B) layout of hidden
    tr_bs2sb<<<MR, 128>>>(out_h, hsb);
    // 12-13. logits = [x1 | hsb] @ V_w^T  (V_w is (128,1024))
    gemm_nt<EP_NONE, false><<<dim3(1, 64), 256>>>(x1, 512, Vw, 1024, nullptr,
                                                  nullptr, 0, lg, 128, 512);
    gemm_nt<EP_NONE, true><<<dim3(1, 64), 256>>>(hsb, 512, Vw + 512, 1024, nullptr,
                                                 nullptr, 0, lg, 128, 512);
    // 14. softmax over 128
    softmax128<<<MR / 8, 256>>>(lg);
    // 15. x2 = 0.5*(x1 + probs @ U_w^T)
    gemm_nt<EP_HALF, false><<<dim3(4, 64), 256>>>(lg, 128, Uw, 128, nullptr,
                                                  x1, 512, x2, 512, 128);
    // 16. stack_inp = nonsat(hidden @ D_w^T + D_b)
    gemm_nt<EP_NONSAT, false><<<dim3(1, 64), 256>>>(out_h, 512, Dw, 512, Db,
                                                    nullptr, 0, si, 128, 512);
    // 17. controls
    controls_kernel<<<MR, 128>>>(out_h, Aw, Ab, ct);
    // 18. stack update -> out_s
    stack_kernel<<<MR, 256>>>(s_prev, si, ct, out_s);
    // 19. h2 = LN(x2)
    ln_kernel<<<MR, 128>>>(x2, ln2g, ln2b, h2);
    // 20-21. FFN: out_x = x2 + relu(h2@ffw1^T + ffb1)@ffw2^T + ffb2
    gemm_nt<EP_RELU, false><<<dim3(16, 64), 256>>>(h2, 512, ffw1, 512, ffb1,
                                                   nullptr, 0, ff, 2048, 512);
    gemm_nt<EP_RESID, false><<<dim3(4, 64), 256>>>(ff, 2048, ffw2, 2048, ffb2,
                                                   x2, 512, out_x, 512, 2048);
    (void)in_sizes; (void)n_in; (void)out_size;
}

// round 8
// speedup vs baseline: 1.0028x; 1.0028x over previous
#include <cuda_runtime.h>
#include <cuda_bf16.h>

#define RESTRICT __restrict__

constexpr int SEQL = 512, NB = 16, EMB = 512, MR = SEQL * NB;
constexpr int QKVLD = NB * 3 * EMB;   // 24576: per-s stride in qkv buffer

// ---- one big static scratch (377 MB), partitioned by offsets ----
__device__ float g_scratch[94396416];
// offsets (floats)
constexpr size_t O_LN1 = 0;           // 8192x512
constexpr size_t O_QKV = 4194304;     // 8192x1536
constexpr size_t O_SC  = 16777216;    // 128 heads x 512x512
constexpr size_t O_O   = 50331648;    // 8192x512 (S,B)
constexpr size_t O_X1  = 54525952;    // 8192x512 (S,B)
constexpr size_t O_XB  = 58720256;    // 8192x512 (B,S)
constexpr size_t O_HSB = 62914560;    // 8192x512 (S,B)
constexpr size_t O_LG  = 67108864;    // 8192x128
constexpr size_t O_X2  = 68157440;    // 8192x512 (S,B)
constexpr size_t O_H2  = 72351744;    // 8192x512
constexpr size_t O_FF  = 76546048;    // 8192x2048
constexpr size_t O_SI  = 93323264;    // 8192x128
constexpr size_t O_CT  = 94371840;    // 8192x3

// ---- f32x2 helpers ----
__device__ __forceinline__ unsigned long long pk2(float x, float y) {
    unsigned long long r;
    asm("mov.b64 %0, {%1, %2};" : "=l"(r) : "f"(x), "f"(y));
    return r;
}
__device__ __forceinline__ void ffma2(unsigned long long& d, unsigned long long a,
                                      unsigned long long b) {
    asm("fma.rn.f32x2 %0, %1, %2, %0;" : "+l"(d) : "l"(a), "l"(b));
}
__device__ __forceinline__ float2 upk2(unsigned long long v) {
    float2 r;
    asm("mov.b64 {%0, %1}, %2;" : "=f"(r.x), "=f"(r.y) : "l"(v));
    return r;
}

__device__ __forceinline__ float nonsat_f(float x) {
    float y = x;
#pragma unroll
    for (int i = 0; i < 8; i++) {
        float y2 = y * y;
        y = __fdividef(__fmaf_rn(0.66666667f * y2, y, x), y2 + 1.0f);
    }
    return y;
}

// ---- LayerNorm: block(128) per row of 512 ----
__global__ void ln_kernel(const float* RESTRICT in, const float* RESTRICT g,
                          const float* RESTRICT b, float* RESTRICT out) {
    int row = blockIdx.x, t = threadIdx.x;
    float4 v = ((const float4*)(in + (size_t)row * EMB))[t];
    float s = v.x + v.y + v.z + v.w;
    float sq = v.x * v.x + v.y * v.y + v.z * v.z + v.w * v.w;
    __shared__ float ss[4], ssq[4];
#pragma unroll
    for (int o = 16; o > 0; o >>= 1) {
        s += __shfl_down_sync(0xffffffffu, s, o);
        sq += __shfl_down_sync(0xffffffffu, sq, o);
    }
    int w = t >> 5, l = t & 31;
    if (l == 0) { ss[w] = s; ssq[w] = sq; }
    __syncthreads();
    s = ss[0] + ss[1] + ss[2] + ss[3];
    sq = ssq[0] + ssq[1] + ssq[2] + ssq[3];
    float mean = s * (1.0f / EMB);
    float rstd = rsqrtf(sq * (1.0f / EMB) - mean * mean + 1e-5f);
    float4 gv = ((const float4*)g)[t], bv = ((const float4*)b)[t];
    float4 o4;
    o4.x = (v.x - mean) * rstd * gv.x + bv.x;
    o4.y = (v.y - mean) * rstd * gv.y + bv.y;
    o4.z = (v.z - mean) * rstd * gv.z + bv.z;
    o4.w = (v.w - mean) * rstd * gv.w + bv.w;
    ((float4*)(out + (size_t)row * EMB))[t] = o4;
}

// ---- generic NT GEMM: C = A(MxK)*W(NxK)^T, 128x128x8 tiles, 256 thr ----
enum { EP_NONE = 0, EP_RELU, EP_NONSAT, EP_RESID, EP_HALF };

template <int EPI, bool ACCUM>
__global__ void __launch_bounds__(256) gemm_nt(
    const float* RESTRICT A, int lda, const float* RESTRICT W, int ldw,
    const float* RESTRICT bias, const float* RESTRICT resid, int ldr,
    float* RESTRICT C, int ldc, int K) {
    __shared__ float As[8][132], Bs[8][132];
    const int tid = threadIdx.x;
    const int tr = tid >> 4, tc = tid & 15;
    const int lrow = tid >> 1, lk = (tid & 1) * 4;
    const float* Ab = A + (size_t)(blockIdx.y * 128 + lrow) * lda + lk;
    const float* Wb = W + (size_t)(blockIdx.x * 128 + lrow) * ldw + lk;

    unsigned long long acc[8][4];
#pragma unroll
    for (int i = 0; i < 8; i++)
#pragma unroll
        for (int j = 0; j < 4; j++) acc[i][j] = 0ull;

    float4 av = *(const float4*)Ab;
    float4 wv = *(const float4*)Wb;
    for (int k0 = 0; k0 < K; k0 += 8) {
        As[lk + 0][lrow] = av.x; As[lk + 1][lrow] = av.y;
        As[lk + 2][lrow] = av.z; As[lk + 3][lrow] = av.w;
        Bs[lk + 0][lrow] = wv.x; Bs[lk + 1][lrow] = wv.y;
        Bs[lk + 2][lrow] = wv.z; Bs[lk + 3][lrow] = wv.w;
        __syncthreads();
        if (k0 + 8 < K) {
            av = *(const float4*)(Ab + k0 + 8);
            wv = *(const float4*)(Wb + k0 + 8);
        }
#pragma unroll
        for (int kk = 0; kk < 8; kk++) {
            float a[8];
            unsigned long long b2[4];
#pragma unroll
            for (int i = 0; i < 8; i++) a[i] = As[kk][tr * 8 + i];
#pragma unroll
            for (int j = 0; j < 4; j++)
                b2[j] = pk2(Bs[kk][tc * 8 + 2 * j], Bs[kk][tc * 8 + 2 * j + 1]);
#pragma unroll
            for (int i = 0; i < 8; i++) {
                unsigned long long a2 = pk2(a[i], a[i]);
#pragma unroll
                for (int j = 0; j < 4; j++) ffma2(acc[i][j], a2, b2[j]);
            }
        }
        __syncthreads();
    }
    const int m0 = blockIdx.y * 128 + tr * 8;
    const int n0 = blockIdx.x * 128 + tc * 8;
#pragma unroll
    for (int i = 0; i < 8; i++) {
        float v[8];
#pragma unroll
        for (int j = 0; j < 4; j++) {
            float2 p = upk2(acc[i][j]);
            v[2 * j] = p.x; v[2 * j + 1] = p.y;
        }
        if (bias) {
#pragma unroll
            for (int j = 0; j < 8; j++) v[j] += bias[n0 + j];
        }
        float* crow = C + (size_t)(m0 + i) * ldc + n0;
        if (ACCUM) {
            float4 c0 = *(const float4*)crow, c1 = *(const float4*)(crow + 4);
            v[0] += c0.x; v[1] += c0.y; v[2] += c0.z; v[3] += c0.w;
            v[4] += c1.x; v[5] += c1.y; v[6] += c1.z; v[7] += c1.w;
        }
        if (EPI == EP_RELU) {
#pragma unroll
            for (int j = 0; j < 8; j++) v[j] = fmaxf(v[j], 0.0f);
        } else if (EPI == EP_NONSAT) {
#pragma unroll
            for (int j = 0; j < 8; j++) v[j] = nonsat_f(v[j]);
        } else if (EPI == EP_RESID) {
            const float* rr = resid + (size_t)(m0 + i) * ldr + n0;
            float4 r0 = *(const float4*)rr, r1 = *(const float4*)(rr + 4);
            v[0] += r0.x; v[1] += r0.y; v[2] += r0.z; v[3] += r0.w;
            v[4] += r1.x; v[5] += r1.y; v[6] += r1.z; v[7] += r1.w;
        } else if (EPI == EP_HALF) {
            const float* rr = resid + (size_t)(m0 + i) * ldr + n0;
            float4 r0 = *(const float4*)rr, r1 = *(const float4*)(rr + 4);
            v[0] = 0.5f * (v[0] + r0.x); v[1] = 0.5f * (v[1] + r0.y);
            v[2] = 0.5f * (v[2] + r0.z); v[3] = 0.5f * (v[3] + r0.w);
            v[4] = 0.5f * (v[4] + r1.x); v[5] = 0.5f * (v[5] + r1.y);
            v[6] = 0.5f * (v[6] + r1.z); v[7] = 0.5f * (v[7] + r1.w);
        }
        *(float4*)crow = make_float4(v[0], v[1], v[2], v[3]);
        *(float4*)(crow + 4) = make_float4(v[4], v[5], v[6], v[7]);
    }
}

// ---- attention scores: per (b,h) QK^T, K=64, scaled + causal ----
__global__ void __launch_bounds__(256) attn_scores(const float* RESTRICT qkv,
                                                   float* RESTRICT scores) {
    __shared__ float As[8][132], Bs[8][132];
    const int head = blockIdx.z, b = head >> 3, h = head & 7;
    const int tid = threadIdx.x;
    const int tr = tid >> 4, tc = tid & 15;
    const int lrow = tid >> 1, lk = (tid & 1) * 4;
    const float* qb = qkv + (size_t)(blockIdx.y * 128 + lrow) * QKVLD + b * 1536 + h * 64 + lk;
    const float* kb = qkv + (size_t)(blockIdx.x * 128 + lrow) * QKVLD + b * 1536 + 512 + h * 64 + lk;
    unsigned long long acc[8][4];
#pragma unroll
    for (int i = 0; i < 8; i++)
#pragma unroll
        for (int j = 0; j < 4; j++) acc[i][j] = 0ull;
    float4 av = *(const float4*)qb;
    float4 wv = *(const float4*)kb;
    for (int k0 = 0; k0 < 64; k0 += 8) {
        As[lk + 0][lrow] = av.x; As[lk + 1][lrow] = av.y;
        As[lk + 2][lrow] = av.z; As[lk + 3][lrow] = av.w;
        Bs[lk + 0][lrow] = wv.x; Bs[lk + 1][lrow] = wv.y;
        Bs[lk + 2][lrow] = wv.z; Bs[lk + 3][lrow] = wv.w;
        __syncthreads();
        if (k0 + 8 < 64) { av = *(const float4*)(qb + k0 + 8); wv = *(const float4*)(kb + k0 + 8); }
#pragma unroll
        for (int kk = 0; kk < 8; kk++) {
            float a[8];
            unsigned long long b2[4];
#pragma unroll
            for (int i = 0; i < 8; i++) a[i] = As[kk][tr * 8 + i];
#pragma unroll
            for (int j = 0; j < 4; j++)
                b2[j] = pk2(Bs[kk][tc * 8 + 2 * j], Bs[kk][tc * 8 + 2 * j + 1]);
#pragma unroll
            for (int i = 0; i < 8; i++) {
                unsigned long long a2 = pk2(a[i], a[i]);
#pragma unroll
                for (int j = 0; j < 4; j++) ffma2(acc[i][j], a2, b2[j]);
            }
        }
        __syncthreads();
    }
    const int q0 = blockIdx.y * 128 + tr * 8, kk0 = blockIdx.x * 128 + tc * 8;
    const float NEGINF = __int_as_float(0xff800000);
    float* sbase = scores + (size_t)head * SEQL * SEQL;
#pragma unroll
    for (int i = 0; i < 8; i++) {
        int q = q0 + i;
        float v[8];
#pragma unroll
        for (int j = 0; j < 4; j++) {
            float2 p = upk2(acc[i][j]);
            v[2 * j] = p.x; v[2 * j + 1] = p.y;
        }
#pragma unroll
        for (int j = 0; j < 8; j++) {
            v[j] *= 0.125f;
            if (kk0 + j > q) v[j] = NEGINF;
        }
        float* crow = sbase + (size_t)q * SEQL + kk0;
        *(float4*)crow = make_float4(v[0], v[1], v[2], v[3]);
        *(float4*)(crow + 4) = make_float4(v[4], v[5], v[6], v[7]);
    }
}

// ---- softmax over 512, warp per row, with key mask ----
__global__ void softmax512(float* RESTRICT sc, const unsigned char* RESTRICT mask) {
    int row = blockIdx.x * 8 + (threadIdx.x >> 5);     // row in [0, 128*512)
    int l = threadIdx.x & 31;
    int b = row >> 12;
    const float NEGINF = __int_as_float(0xff800000);
    float4* p = (float4*)(sc + (size_t)row * SEQL);
    const uchar4* m4 = (const uchar4*)(mask + b * SEQL);
    float4 v[4];
    float mx = -3.402823466e38f;
#pragma unroll
    for (int w = 0; w < 4; w++) {
        int i = l + w * 32;
        v[w] = p[i];
        uchar4 m = m4[i];
        if (m.x) v[w].x = NEGINF;
        if (m.y) v[w].y = NEGINF;
        if (m.z) v[w].z = NEGINF;
        if (m.w) v[w].w = NEGINF;
        mx = fmaxf(mx, fmaxf(fmaxf(v[w].x, v[w].y), fmaxf(v[w].z, v[w].w)));
    }
#pragma unroll
    for (int o = 16; o > 0; o >>= 1) mx = fmaxf(mx, __shfl_xor_sync(0xffffffffu, mx, o));
    float s = 0.0f;
#pragma unroll
    for (int w = 0; w < 4; w++) {
        v[w].x = __expf(v[w].x - mx); v[w].y = __expf(v[w].y - mx);
        v[w].z = __expf(v[w].z - mx); v[w].w = __expf(v[w].w - mx);
        s += v[w].x + v[w].y + v[w].z + v[w].w;
    }
#pragma unroll
    for (int o = 16; o > 0; o >>= 1) s += __shfl_xor_sync(0xffffffffu, s, o);
    float inv = __fdividef(1.0f, s);
#pragma unroll
    for (int w = 0; w < 4; w++) {
        v[w].x *= inv; v[w].y *= inv; v[w].z *= inv; v[w].w *= inv;
        p[l + w * 32] = v[w];
    }
}

// ---- per-head O = P(512x512) @ V(512x64) -> (S,B,E) ----
__global__ void __launch_bounds__(256) attn_av(const float* RESTRICT qkv,
                                               const float* RESTRICT scores,
                                               float* RESTRICT O) {
    __shared__ float As[8][132], Bs[8][68];
    const int head = blockIdx.z, b = head >> 3, h = head & 7;
    const int tid = threadIdx.x;
    const int tr = tid >> 4, tc = tid & 15;
    const int lrow = tid >> 1, lk = (tid & 1) * 4;
    const float* sc = scores + (size_t)head * SEQL * SEQL +
                      (size_t)(blockIdx.y * 128 + lrow) * SEQL + lk;
    const float* vbase = qkv + (size_t)b * 1536 + 1024 + (size_t)h * 64;
    const int brow = tid >> 4, bcol = (tid & 15) * 4;
    unsigned long long acc[8][2];
#pragma unroll
    for (int i = 0; i < 8; i++) { acc[i][0] = 0ull; acc[i][1] = 0ull; }
    float4 av = *(const float4*)sc;
    float4 vv = make_float4(0, 0, 0, 0);
    if (tid < 128) vv = *(const float4*)(vbase + (size_t)brow * QKVLD + bcol);
    for (int k0 = 0; k0 < 512; k0 += 8) {
        As[lk + 0][lrow] = av.x; As[lk + 1][lrow] = av.y;
        As[lk + 2][lrow] = av.z; As[lk + 3][lrow] = av.w;
        if (tid < 128) *(float4*)&Bs[brow][bcol] = vv;
        __syncthreads();
        if (k0 + 8 < 512) {
            av = *(const float4*)(sc + k0 + 8);
            if (tid < 128)
                vv = *(const float4*)(vbase + (size_t)(k0 + 8 + brow) * QKVLD + bcol);
        }
#pragma unroll
        for (int kk = 0; kk < 8; kk++) {
            float a[8];
            unsigned long long b0 = pk2(Bs[kk][tc * 4 + 0], Bs[kk][tc * 4 + 1]);
            unsigned long long b1 = pk2(Bs[kk][tc * 4 + 2], Bs[kk][tc * 4 + 3]);
#pragma unroll
            for (int i = 0; i < 8; i++) a[i] = As[kk][tr * 8 + i];
#pragma unroll
            for (int i = 0; i < 8; i++) {
                unsigned long long a2 = pk2(a[i], a[i]);
                ffma2(acc[i][0], a2, b0);
                ffma2(acc[i][1], a2, b1);
            }
        }
        __syncthreads();
    }
    const int q0 = blockIdx.y * 128 + tr * 8, d0 = tc * 4;
#pragma unroll
    for (int i = 0; i < 8; i++) {
        float2 p0 = upk2(acc[i][0]), p1 = upk2(acc[i][1]);
        *(float4*)(O + (size_t)((q0 + i) * NB + b) * EMB + h * 64 + d0) =
            make_float4(p0.x, p0.y, p1.x, p1.y);
    }
}

// ---- layout transposes, block(128) per out row ----
__global__ void tr_sb2bs(const float* RESTRICT in, float* RESTRICT out) {
    int r = blockIdx.x, b = r >> 9, s = r & 511;
    ((float4*)(out + (size_t)r * EMB))[threadIdx.x] =
        ((const float4*)(in + (size_t)(s * NB + b) * EMB))[threadIdx.x];
}
__global__ void tr_bs2sb(const float* RESTRICT in, float* RESTRICT out) {
    int r = blockIdx.x, s = r >> 4, b = r & 15;   // out row r = s*16+b
    ((float4*)(out + (size_t)r * EMB))[threadIdx.x] =
        ((const float4*)(in + (size_t)(b * SEQL + s) * EMB))[threadIdx.x];
}

// ---- softmax over 128, warp per row ----
__global__ void softmax128(float* RESTRICT p) {
    int row = blockIdx.x * 8 + (threadIdx.x >> 5);
    int l = threadIdx.x & 31;
    float4 v = ((float4*)(p + (size_t)row * 128))[l];
    float mx = fmaxf(fmaxf(v.x, v.y), fmaxf(v.z, v.w));
#pragma unroll
    for (int o = 16; o > 0; o >>= 1) mx = fmaxf(mx, __shfl_xor_sync(0xffffffffu, mx, o));
    v.x = __expf(v.x - mx); v.y = __expf(v.y - mx);
    v.z = __expf(v.z - mx); v.w = __expf(v.w - mx);
    float s = v.x + v.y + v.z + v.w;
#pragma unroll
    for (int o = 16; o > 0; o >>= 1) s += __shfl_xor_sync(0xffffffffu, s, o);
    float inv = __fdividef(1.0f, s);
    v.x *= inv; v.y *= inv; v.z *= inv; v.w *= inv;
    ((float4*)(p + (size_t)row * 128))[l] = v;
}

// ---- controls = softmax(hidden @ A_w^T + A_b), block(128) per row ----
__global__ void controls_kernel(const float* RESTRICT hid, const float* RESTRICT Aw,
                                const float* RESTRICT Ab, float* RESTRICT ctl) {
    int r = blockIdx.x, t = threadIdx.x;
    float4 h = ((const float4*)(hid + (size_t)r * EMB))[t];
    float4 a0 = ((const float4*)Aw)[t];
    float4 a1 = ((const float4*)(Aw + 512))[t];
    float4 a2 = ((const float4*)(Aw + 1024))[t];
    float p0 = h.x * a0.x + h.y * a0.y + h.z * a0.z + h.w * a0.w;
    float p1 = h.x * a1.x + h.y * a1.y + h.z * a1.z + h.w * a1.w;
    float p2 = h.x * a2.x + h.y * a2.y + h.z * a2.z + h.w * a2.w;
#pragma unroll
    for (int o = 16; o > 0; o >>= 1) {
        p0 += __shfl_down_sync(0xffffffffu, p0, o);
        p1 += __shfl_down_sync(0xffffffffu, p1, o);
        p2 += __shfl_down_sync(0xffffffffu, p2, o);
    }
    __shared__ float sm[3][4];
    int w = t >> 5, l = t & 31;
    if (l == 0) { sm[0][w] = p0; sm[1][w] = p1; sm[2][w] = p2; }
    __syncthreads();
    if (t == 0) {
        float c0 = sm[0][0] + sm[0][1] + sm[0][2] + sm[0][3] + Ab[0];
        float c1 = sm[1][0] + sm[1][1] + sm[1][2] + sm[1][3] + Ab[1];
        float c2 = sm[2][0] + sm[2][1] + sm[2][2] + sm[2][3] + Ab[2];
        float m = fmaxf(c0, fmaxf(c1, c2));
        float e0 = __expf(c0 - m), e1 = __expf(c1 - m), e2 = __expf(c2 - m);
        float inv = __fdividef(1.0f, e0 + e1 + e2);
        ctl[r * 3 + 0] = e0 * inv; ctl[r * 3 + 1] = e1 * inv; ctl[r * 3 + 2] = e2 * inv;
    }
}

// ---- stack update, block(256) per (b,s) row ----
__global__ void stack_kernel(const float* RESTRICT prev, const float* RESTRICT sinp,
                             const float* RESTRICT ctl, float* RESTRICT out) {
    int r = blockIdx.x;
    __shared__ float sp[48 * 128];
    __shared__ float si[128];
    const float4* pin = (const float4*)(prev + (size_t)r * 6144);
    float4* sp4 = (float4*)sp;
    for (int i = threadIdx.x; i < 1536; i += 256) sp4[i] = pin[i];
    if (threadIdx.x < 32)
        ((float4*)si)[threadIdx.x] = ((const float4*)(sinp + (size_t)r * 128))[threadIdx.x];
    __syncthreads();
    float apu = ctl[r * 3 + 0], apo = ctl[r * 3 + 1], ano = ctl[r * 3 + 2];
    float4* o4 = (float4*)(out + (size_t)r * 6144);
    for (int i = threadIdx.x; i < 1536; i += 256) {
        int d = i >> 5, w4 = i & 31;
        float4 pv = sp4[i];
        float4 up = (d == 0) ? ((float4*)si)[w4] : sp4[i - 32];
        float4 dn = (d == 47) ? make_float4(0, 0, 0, 0) : sp4[i + 32];
        float4 o;
        o.x = ano * pv.x + apu * up.x + apo * dn.x;
        o.y = ano * pv.y + apu * up.y + apo * dn.y;
        o.z = ano * pv.z + apu * up.z + apo * dn.z;
        o.w = ano * pv.w + apu * up.w + apo * dn.w;
        o4[i] = o;
    }
}

extern "C" void kernel_launch(void* const* d_in, const int* in_sizes, int n_in,
                              void* d_out, int out_size) {
    const float* x_in   = (const float*)d_in[0];
    const float* h_prev = (const float*)d_in[1];
    const float* s_prev = (const float*)d_in[2];
    const unsigned char* k_mask = (const unsigned char*)d_in[3];
    const float* in_w   = (const float*)d_in[4];
    const float* in_b   = (const float*)d_in[5];
    const float* out_w  = (const float*)d_in[6];
    const float* out_b  = (const float*)d_in[7];
    const float* ln1g = (const float*)d_in[8],  *ln1b = (const float*)d_in[9];
    const float* ln2g = (const float*)d_in[10], *ln2b = (const float*)d_in[11];
    const float* ffw1 = (const float*)d_in[12], *ffb1 = (const float*)d_in[13];
    const float* ffw2 = (const float*)d_in[14], *ffb2 = (const float*)d_in[15];
    const float* Ww = (const float*)d_in[16], *Wb = (const float*)d_in[17];
    const float* Rw = (const float*)d_in[18], *Rb = (const float*)d_in[19];
    const float* Pw = (const float*)d_in[20], *Pb = (const float*)d_in[21];
    const float* Vw = (const float*)d_in[22];
    const float* Uw = (const float*)d_in[23];
    const float* Aw = (const float*)d_in[24], *Ab = (const float*)d_in[25];
    const float* Dw = (const float*)d_in[26], *Db = (const float*)d_in[27];

    float* sb;
    cudaGetSymbolAddress((void**)&sb, g_scratch);
    float* ln1 = sb + O_LN1;  float* qkv = sb + O_QKV;  float* scr = sb + O_SC;
    float* obuf = sb + O_O;   float* x1 = sb + O_X1;    float* xb = sb + O_XB;
    float* hsb = sb + O_HSB;  float* lg = sb + O_LG;    float* x2 = sb + O_X2;
    float* h2 = sb + O_H2;    float* ff = sb + O_FF;    float* si = sb + O_SI;
    float* ct = sb + O_CT;

    float* out_x = (float*)d_out;
    float* out_h = out_x + (size_t)MR * EMB;
    float* out_s = out_h + (size_t)MR * EMB;

    // 1. ln1 = LN(x_in)
    ln_kernel<<<MR, 128>>>(x_in, ln1g, ln1b, ln1);
    // 2. qkv
    gemm_nt<EP_NONE, false><<<dim3(12, 64), 256>>>(ln1, 512, in_w, 512, in_b,
                                                   nullptr, 0, qkv, 1536, 512);
    // 3-5. attention
    attn_scores<<<dim3(4, 4, 128), 256>>>(qkv, scr);
    softmax512<<<128 * 512 / 8, 256>>>(scr, k_mask);
    attn_av<<<dim3(1, 4, 128), 256>>>(qkv, scr, obuf);
    // 6. x1 = x_in + o @ out_w^T + out_b
    gemm_nt<EP_RESID, false><<<dim3(4, 64), 256>>>(obuf, 512, out_w, 512, out_b,
                                                   x_in, 512, x1, 512, 512);
    // 7. xb = (B,S) layout of x1
    tr_sb2bs<<<MR, 128>>>(x1, xb);
    // 8-10. hidden = nonsat(xb@W^T + Wb + hp@R^T + Rb + stack0@P^T + Pb) -> out_h
    gemm_nt<EP_NONE, false><<<dim3(4, 64), 256>>>(xb, 512, Ww, 512, Wb,
                                                  nullptr, 0, out_h, 512, 512);
    gemm_nt<EP_NONE, true><<<dim3(4, 64), 256>>>(h_prev, 512, Rw, 512, Rb,
                                                 nullptr, 0, out_h, 512, 512);
    gemm_nt<EP_NONSAT, true><<<dim3(4, 64), 256>>>(s_prev, 6144, Pw, 128, Pb,
                                                   nullptr, 0, out_h, 512, 128);
    // 11. hsb = (S,B) layout of hidden
    tr_bs2sb<<<MR, 128>>>(out_h, hsb);
    // 12-13. logits = [x1 | hsb] @ V_w^T  (V_w is (128,1024))
    gemm_nt<EP_NONE, false><<<dim3(1, 64), 256>>>(x1, 512, Vw, 1024, nullptr,
                                                  nullptr, 0, lg, 128, 512);
    gemm_nt<EP_NONE, true><<<dim3(1, 64), 256>>>(hsb, 512, Vw + 512, 1024, nullptr,
                                                 nullptr, 0, lg, 128, 512);
    // 14. softmax over 128
    softmax128<<<MR / 8, 256>>>(lg);
    // 15. x2 = 0.5*(x1 + probs @ U_w^T)
    gemm_nt<EP_HALF, false><<<dim3(4, 64), 256>>>(lg, 128, Uw, 128, nullptr,
                                                  x1, 512, x2, 512, 128);
    // 16. stack_inp = nonsat(hidden @ D_w^T + D_b)
    gemm_nt<EP_NONSAT, false><<<dim3(1, 64), 256>>>(out_h, 512, Dw, 512, Db,
                                                    nullptr, 0, si, 128, 512);
    // 17. controls
    controls_kernel<<<MR, 128>>>(out_h, Aw, Ab, ct);
    // 18. stack update -> out_s
    stack_kernel<<<MR, 256>>>(s_prev, si, ct, out_s);
    // 19. h2 = LN(x2)
    ln_kernel<<<MR, 128>>>(x2, ln2g, ln2b, h2);
    // 20-21. FFN: out_x = x2 + relu(h2@ffw1^T + ffb1)@ffw2^T + ffb2
    gemm_nt<EP_RELU, false><<<dim3(16, 64), 256>>>(h2, 512, ffw1, 512, ffb1,
                                                   nullptr, 0, ff, 2048, 512);
    gemm_nt<EP_RESID, false><<<dim3(4, 64), 256>>>(ff, 2048, ffw2, 2048, ffb2,
                                                   x2, 512, out_x, 512, 2048);
    (void)in_sizes; (void)n_in; (void)out_size;
}